// round 2
// baseline (speedup 1.0000x reference)
#include <cuda_runtime.h>
#include <stdint.h>

// Problem dims
#define B_ROWS 8192
#define D_IN   784
#define H_DIM  1024
#define C_OUT  10
#define NW     32          // 32-bit words per bit-row (1024 bits; x uses 25, rest zero-pad)

// ---------------- scratch (device globals; no allocation allowed) ----------------
__device__ uint32_t g_xbits[B_ROWS * NW];
__device__ uint32_t g_hA[B_ROWS * NW];
__device__ uint32_t g_hB[B_ROWS * NW];
__device__ uint32_t g_wt1[NW * H_DIM];   // transposed: [k][o]
__device__ uint32_t g_wt2[NW * H_DIM];
__device__ uint32_t g_wt3[NW * H_DIM];
__device__ float    g_P1[H_DIM];
__device__ float    g_P2[H_DIM];
__device__ float    g_P3[H_DIM];
__device__ uint32_t g_wfcb[C_OUT * NW];
__device__ float    g_sfc;

// ---------------- input packing: bit = (x >= 0.5)  (sign(2x-1), sign(0)=+1) ------
__global__ void pack_x_kernel(const float* __restrict__ x) {
    int wg   = (blockIdx.x * blockDim.x + threadIdx.x) >> 5;  // global warp id
    int lane = threadIdx.x & 31;
    int row  = wg >> 5;         // /32 words per row
    int k    = wg & 31;
    int f    = k * 32 + lane;
    unsigned pred = 0;
    if (f < D_IN) pred = (x[row * D_IN + f] >= 0.5f) ? 1u : 0u;
    unsigned word = __ballot_sync(0xFFFFFFFFu, pred);
    if (lane == 0) g_xbits[row * NW + k] = word;
}

// ---------------- weight packing (transposed [k][o]), bit = (w >= 0) -------------
__global__ void pack_w_kernel(const float* __restrict__ w, int K, int layer) {
    uint32_t* WT = (layer == 1) ? g_wt1 : (layer == 2) ? g_wt2 : g_wt3;
    int wg   = (blockIdx.x * blockDim.x + threadIdx.x) >> 5;
    int lane = threadIdx.x & 31;
    int o    = wg >> 5;
    int k    = wg & 31;
    int f    = k * 32 + lane;
    unsigned pred = 0;
    if (f < K) pred = (w[o * K + f] >= 0.0f) ? 1u : 0u;
    unsigned word = __ballot_sync(0xFFFFFFFFu, pred);
    if (lane == 0) WT[k * H_DIM + o] = word;
}

// ---------------- per-channel popcount thresholds --------------------------------
// y = (h - m)*g*rsqrt(v+eps) + be >= 0, h = scale*d + b, d = K - 2p
// ->  bit = ( p <= (K - T)/2 ),  T = (m - be/rg - b)/scale
__global__ void thr_kernel(const float* __restrict__ w, const float* __restrict__ b,
                           const float* __restrict__ g, const float* __restrict__ be,
                           const float* __restrict__ m, const float* __restrict__ v,
                           int K, int layer) {
    __shared__ float sm[256];
    int o = blockIdx.x;
    float s = 0.0f;
    for (int i = threadIdx.x; i < K; i += 256) s += fabsf(w[o * K + i]);
    sm[threadIdx.x] = s;
    __syncthreads();
    for (int off = 128; off > 0; off >>= 1) {
        if (threadIdx.x < off) sm[threadIdx.x] += sm[threadIdx.x + off];
        __syncthreads();
    }
    if (threadIdx.x == 0) {
        float* P = (layer == 1) ? g_P1 : (layer == 2) ? g_P2 : g_P3;
        float sc = sm[0] / (float)K;
        float rg = g[o] * rsqrtf(v[o] + 1e-5f);
        float T  = (m[o] - be[o] / rg - b[o]) / sc;
        P[o] = ((float)K - T) * 0.5f;
    }
}

// ---------------- final-layer scale (per-tensor mean |wfc|) ----------------------
__global__ void fcscale_kernel(const float* __restrict__ wfc) {
    __shared__ float sm[256];
    float s = 0.0f;
    for (int i = threadIdx.x; i < C_OUT * H_DIM; i += 256) s += fabsf(wfc[i]);
    sm[threadIdx.x] = s;
    __syncthreads();
    for (int off = 128; off > 0; off >>= 1) {
        if (threadIdx.x < off) sm[threadIdx.x] += sm[threadIdx.x + off];
        __syncthreads();
    }
    if (threadIdx.x == 0) g_sfc = sm[0] / (float)(C_OUT * H_DIM);
}

__global__ void pack_wfc_kernel(const float* __restrict__ wfc) {
    int wg   = (blockIdx.x * blockDim.x + threadIdx.x) >> 5;  // 320 warps total
    int lane = threadIdx.x & 31;
    int c    = wg >> 5;
    int k    = wg & 31;
    int f    = k * 32 + lane;
    unsigned pred = (wfc[c * H_DIM + f] >= 0.0f) ? 1u : 0u;
    unsigned word = __ballot_sync(0xFFFFFFFFu, pred);
    if (lane == 0) g_wfcb[c * NW + k] = word;
}

// ---------------- hot kernel: bit-GEMM + BN/sign epilogue ------------------------
// Each warp owns one out-word (32 output channels, one per lane), keeps the 32
// transposed weight words in registers, and streams 64 rows. Row bits load as
// 8 uniform LDG.128 (L1 broadcast). Epilogue: float compare + ballot -> 1 STG.
__global__ void __launch_bounds__(256) layer_kernel(int layer) {
    const uint32_t* I  = (layer == 1) ? g_xbits : (layer == 2) ? g_hA : g_hB;
    uint32_t*       O  = (layer == 1) ? g_hA   : (layer == 2) ? g_hB : g_hA;
    const uint32_t* WT = (layer == 1) ? g_wt1  : (layer == 2) ? g_wt2 : g_wt3;
    const float*    P  = (layer == 1) ? g_P1   : (layer == 2) ? g_P2  : g_P3;

    int warp = threadIdx.x >> 5;
    int lane = threadIdx.x & 31;
    int ow   = blockIdx.y * 8 + warp;     // out-word index 0..31
    int row0 = blockIdx.x * 64;
    int o    = (ow << 5) + lane;          // this lane's output channel

    uint32_t w[32];
#pragma unroll
    for (int k = 0; k < 32; k++) w[k] = WT[k * H_DIM + o];
    float thr = P[o];

    for (int r = 0; r < 64; r++) {
        int row = row0 + r;
        const uint4* arow = reinterpret_cast<const uint4*>(I + row * NW);
        int a0 = 0, a1 = 0, a2 = 0, a3 = 0;
#pragma unroll
        for (int kk = 0; kk < 8; kk++) {
            uint4 a = __ldg(arow + kk);
            a0 += __popc(a.x ^ w[4 * kk + 0]);
            a1 += __popc(a.y ^ w[4 * kk + 1]);
            a2 += __popc(a.z ^ w[4 * kk + 2]);
            a3 += __popc(a.w ^ w[4 * kk + 3]);
        }
        int acc = (a0 + a1) + (a2 + a3);
        unsigned word = __ballot_sync(0xFFFFFFFFu, (float)acc <= thr);
        if (lane == 0) O[row * NW + ow] = word;
    }
}

// ---------------- final FC: out = sfc * (1024 - 2p) + bfc ------------------------
__global__ void fc_kernel(const float* __restrict__ bfc, float* __restrict__ out) {
    int warp = threadIdx.x >> 5;
    int lane = threadIdx.x & 31;
    int row  = blockIdx.x * 8 + warp;
    if (lane < C_OUT) {
        const uint4* arow = reinterpret_cast<const uint4*>(g_hA + row * NW);
        const uint32_t* wb = g_wfcb + lane * NW;
        int acc = 0;
#pragma unroll
        for (int kk = 0; kk < 8; kk++) {
            uint4 a = __ldg(arow + kk);
            acc += __popc(a.x ^ wb[4 * kk + 0]);
            acc += __popc(a.y ^ wb[4 * kk + 1]);
            acc += __popc(a.z ^ wb[4 * kk + 2]);
            acc += __popc(a.w ^ wb[4 * kk + 3]);
        }
        float d = (float)(H_DIM - 2 * acc);
        out[row * C_OUT + lane] = g_sfc * d + bfc[lane];
    }
}

// ---------------- launch --------------------------------------------------------
extern "C" void kernel_launch(void* const* d_in, const int* in_sizes, int n_in,
                              void* d_out, int out_size) {
    const float* x   = (const float*)d_in[0];
    const float* w1  = (const float*)d_in[1];
    const float* b1  = (const float*)d_in[2];
    const float* g1  = (const float*)d_in[3];
    const float* be1 = (const float*)d_in[4];
    const float* m1  = (const float*)d_in[5];
    const float* v1  = (const float*)d_in[6];
    const float* w2  = (const float*)d_in[7];
    const float* b2  = (const float*)d_in[8];
    const float* g2  = (const float*)d_in[9];
    const float* be2 = (const float*)d_in[10];
    const float* m2  = (const float*)d_in[11];
    const float* v2  = (const float*)d_in[12];
    const float* w3  = (const float*)d_in[13];
    const float* b3  = (const float*)d_in[14];
    const float* g3  = (const float*)d_in[15];
    const float* be3 = (const float*)d_in[16];
    const float* m3  = (const float*)d_in[17];
    const float* v3  = (const float*)d_in[18];
    const float* wfc = (const float*)d_in[19];
    const float* bfc = (const float*)d_in[20];
    float* out = (float*)d_out;

    // pack input bits: 8192*32 warps
    pack_x_kernel<<<(B_ROWS * NW) / 8, 256>>>(x);

    // pack weights (transposed) + thresholds
    pack_w_kernel<<<(H_DIM * NW) / 8, 256>>>(w1, D_IN, 1);
    pack_w_kernel<<<(H_DIM * NW) / 8, 256>>>(w2, H_DIM, 2);
    pack_w_kernel<<<(H_DIM * NW) / 8, 256>>>(w3, H_DIM, 3);
    thr_kernel<<<H_DIM, 256>>>(w1, b1, g1, be1, m1, v1, D_IN, 1);
    thr_kernel<<<H_DIM, 256>>>(w2, b2, g2, be2, m2, v2, H_DIM, 2);
    thr_kernel<<<H_DIM, 256>>>(w3, b3, g3, be3, m3, v3, H_DIM, 3);
    fcscale_kernel<<<1, 256>>>(wfc);
    pack_wfc_kernel<<<(C_OUT * NW) / 8, 256>>>(wfc);

    // 3 binary GEMM layers
    dim3 lgrid(B_ROWS / 64, 4);  // 128 row-tiles x 4 owgroups (8 warps each)
    layer_kernel<<<lgrid, 256>>>(1);   // xbits -> hA
    layer_kernel<<<lgrid, 256>>>(2);   // hA -> hB
    layer_kernel<<<lgrid, 256>>>(3);   // hB -> hA

    // final FC
    fc_kernel<<<B_ROWS / 8, 256>>>(bfc, out);
}

// round 3
// speedup vs baseline: 1.0050x; 1.0050x over previous
#include <cuda_runtime.h>
#include <stdint.h>

// Problem dims
#define B_ROWS 8192
#define D_IN   784
#define H_DIM  1024
#define C_OUT  10
#define NW     32          // 32-bit words per bit-row (1024 bits; x uses 25, rest zero-pad)

// ---------------- scratch (device globals; no allocation allowed) ----------------
__device__ uint32_t g_xbits[B_ROWS * NW];
__device__ uint32_t g_hA[B_ROWS * NW];
__device__ uint32_t g_hB[B_ROWS * NW];
__device__ uint32_t g_wt1[NW * H_DIM];   // transposed: [k][o]
__device__ uint32_t g_wt2[NW * H_DIM];
__device__ uint32_t g_wt3[NW * H_DIM];
__device__ float    g_P1[H_DIM];
__device__ float    g_P2[H_DIM];
__device__ float    g_P3[H_DIM];
__device__ uint32_t g_wfcb[C_OUT * NW];
__device__ float    g_sfc;

// ---------------- input packing: bit = (x >= 0.5)  (sign(2x-1), sign(0)=+1) ------
__global__ void pack_x_kernel(const float* __restrict__ x) {
    int wg   = (blockIdx.x * blockDim.x + threadIdx.x) >> 5;  // global warp id
    int lane = threadIdx.x & 31;
    int row  = wg >> 5;         // /32 words per row
    int k    = wg & 31;
    int f    = k * 32 + lane;
    unsigned pred = 0;
    if (f < D_IN) pred = (x[row * D_IN + f] >= 0.5f) ? 1u : 0u;
    unsigned word = __ballot_sync(0xFFFFFFFFu, pred);
    if (lane == 0) g_xbits[row * NW + k] = word;
}

// ---------------- weight packing (transposed [k][o]), bit = (w >= 0) -------------
__global__ void pack_w_kernel(const float* __restrict__ w, int K, int layer) {
    uint32_t* WT = (layer == 1) ? g_wt1 : (layer == 2) ? g_wt2 : g_wt3;
    int wg   = (blockIdx.x * blockDim.x + threadIdx.x) >> 5;
    int lane = threadIdx.x & 31;
    int o    = wg >> 5;
    int k    = wg & 31;
    int f    = k * 32 + lane;
    unsigned pred = 0;
    if (f < K) pred = (w[o * K + f] >= 0.0f) ? 1u : 0u;
    unsigned word = __ballot_sync(0xFFFFFFFFu, pred);
    if (lane == 0) WT[k * H_DIM + o] = word;
}

// ---------------- per-channel popcount thresholds --------------------------------
// y = (h - m)*g*rsqrt(v+eps) + be >= 0, h = scale*d + b, d = K - 2p
// ->  bit = ( p <= (K - T)/2 ),  T = (m - be/rg - b)/scale
__global__ void thr_kernel(const float* __restrict__ w, const float* __restrict__ b,
                           const float* __restrict__ g, const float* __restrict__ be,
                           const float* __restrict__ m, const float* __restrict__ v,
                           int K, int layer) {
    __shared__ float sm[256];
    int o = blockIdx.x;
    float s = 0.0f;
    for (int i = threadIdx.x; i < K; i += 256) s += fabsf(w[o * K + i]);
    sm[threadIdx.x] = s;
    __syncthreads();
    for (int off = 128; off > 0; off >>= 1) {
        if (threadIdx.x < off) sm[threadIdx.x] += sm[threadIdx.x + off];
        __syncthreads();
    }
    if (threadIdx.x == 0) {
        float* P = (layer == 1) ? g_P1 : (layer == 2) ? g_P2 : g_P3;
        float sc = sm[0] / (float)K;
        float rg = g[o] * rsqrtf(v[o] + 1e-5f);
        float T  = (m[o] - be[o] / rg - b[o]) / sc;
        P[o] = ((float)K - T) * 0.5f;
    }
}

// ---------------- final-layer scale (per-tensor mean |wfc|) ----------------------
__global__ void fcscale_kernel(const float* __restrict__ wfc) {
    __shared__ float sm[256];
    float s = 0.0f;
    for (int i = threadIdx.x; i < C_OUT * H_DIM; i += 256) s += fabsf(wfc[i]);
    sm[threadIdx.x] = s;
    __syncthreads();
    for (int off = 128; off > 0; off >>= 1) {
        if (threadIdx.x < off) sm[threadIdx.x] += sm[threadIdx.x + off];
        __syncthreads();
    }
    if (threadIdx.x == 0) g_sfc = sm[0] / (float)(C_OUT * H_DIM);
}

__global__ void pack_wfc_kernel(const float* __restrict__ wfc) {
    int wg   = (blockIdx.x * blockDim.x + threadIdx.x) >> 5;  // 320 warps total
    int lane = threadIdx.x & 31;
    int c    = wg >> 5;
    int k    = wg & 31;
    int f    = k * 32 + lane;
    unsigned pred = (wfc[c * H_DIM + f] >= 0.0f) ? 1u : 0u;
    unsigned word = __ballot_sync(0xFFFFFFFFu, pred);
    if (lane == 0) g_wfcb[c * NW + k] = word;
}

// ---------------- hot kernel: bit-GEMM + BN/sign epilogue ------------------------
// Each warp owns one out-word (32 output channels, one per lane), keeps the 32
// transposed weight words in registers, and streams 64 rows. Row bits load as
// 8 uniform LDG.128 (L1 broadcast). Epilogue: float compare + ballot -> 1 STG.
__global__ void __launch_bounds__(256) layer_kernel(int layer) {
    const uint32_t* I  = (layer == 1) ? g_xbits : (layer == 2) ? g_hA : g_hB;
    uint32_t*       O  = (layer == 1) ? g_hA   : (layer == 2) ? g_hB : g_hA;
    const uint32_t* WT = (layer == 1) ? g_wt1  : (layer == 2) ? g_wt2 : g_wt3;
    const float*    P  = (layer == 1) ? g_P1   : (layer == 2) ? g_P2  : g_P3;

    int warp = threadIdx.x >> 5;
    int lane = threadIdx.x & 31;
    int ow   = blockIdx.y * 8 + warp;     // out-word index 0..31
    int row0 = blockIdx.x * 64;
    int o    = (ow << 5) + lane;          // this lane's output channel

    uint32_t w[32];
#pragma unroll
    for (int k = 0; k < 32; k++) w[k] = WT[k * H_DIM + o];
    float thr = P[o];

    for (int r = 0; r < 64; r++) {
        int row = row0 + r;
        const uint4* arow = reinterpret_cast<const uint4*>(I + row * NW);
        int a0 = 0, a1 = 0, a2 = 0, a3 = 0;
#pragma unroll
        for (int kk = 0; kk < 8; kk++) {
            uint4 a = __ldg(arow + kk);
            a0 += __popc(a.x ^ w[4 * kk + 0]);
            a1 += __popc(a.y ^ w[4 * kk + 1]);
            a2 += __popc(a.z ^ w[4 * kk + 2]);
            a3 += __popc(a.w ^ w[4 * kk + 3]);
        }
        int acc = (a0 + a1) + (a2 + a3);
        unsigned word = __ballot_sync(0xFFFFFFFFu, (float)acc <= thr);
        if (lane == 0) O[row * NW + ow] = word;
    }
}

// ---------------- final FC: out = sfc * (1024 - 2p) + bfc ------------------------
__global__ void fc_kernel(const float* __restrict__ bfc, float* __restrict__ out) {
    int warp = threadIdx.x >> 5;
    int lane = threadIdx.x & 31;
    int row  = blockIdx.x * 8 + warp;
    if (lane < C_OUT) {
        const uint4* arow = reinterpret_cast<const uint4*>(g_hA + row * NW);
        const uint32_t* wb = g_wfcb + lane * NW;
        int acc = 0;
#pragma unroll
        for (int kk = 0; kk < 8; kk++) {
            uint4 a = __ldg(arow + kk);
            acc += __popc(a.x ^ wb[4 * kk + 0]);
            acc += __popc(a.y ^ wb[4 * kk + 1]);
            acc += __popc(a.z ^ wb[4 * kk + 2]);
            acc += __popc(a.w ^ wb[4 * kk + 3]);
        }
        float d = (float)(H_DIM - 2 * acc);
        out[row * C_OUT + lane] = g_sfc * d + bfc[lane];
    }
}

// ---------------- launch --------------------------------------------------------
extern "C" void kernel_launch(void* const* d_in, const int* in_sizes, int n_in,
                              void* d_out, int out_size) {
    const float* x   = (const float*)d_in[0];
    const float* w1  = (const float*)d_in[1];
    const float* b1  = (const float*)d_in[2];
    const float* g1  = (const float*)d_in[3];
    const float* be1 = (const float*)d_in[4];
    const float* m1  = (const float*)d_in[5];
    const float* v1  = (const float*)d_in[6];
    const float* w2  = (const float*)d_in[7];
    const float* b2  = (const float*)d_in[8];
    const float* g2  = (const float*)d_in[9];
    const float* be2 = (const float*)d_in[10];
    const float* m2  = (const float*)d_in[11];
    const float* v2  = (const float*)d_in[12];
    const float* w3  = (const float*)d_in[13];
    const float* b3  = (const float*)d_in[14];
    const float* g3  = (const float*)d_in[15];
    const float* be3 = (const float*)d_in[16];
    const float* m3  = (const float*)d_in[17];
    const float* v3  = (const float*)d_in[18];
    const float* wfc = (const float*)d_in[19];
    const float* bfc = (const float*)d_in[20];
    float* out = (float*)d_out;

    // pack input bits: 8192*32 warps
    pack_x_kernel<<<(B_ROWS * NW) / 8, 256>>>(x);

    // pack weights (transposed) + thresholds
    pack_w_kernel<<<(H_DIM * NW) / 8, 256>>>(w1, D_IN, 1);
    pack_w_kernel<<<(H_DIM * NW) / 8, 256>>>(w2, H_DIM, 2);
    pack_w_kernel<<<(H_DIM * NW) / 8, 256>>>(w3, H_DIM, 3);
    thr_kernel<<<H_DIM, 256>>>(w1, b1, g1, be1, m1, v1, D_IN, 1);
    thr_kernel<<<H_DIM, 256>>>(w2, b2, g2, be2, m2, v2, H_DIM, 2);
    thr_kernel<<<H_DIM, 256>>>(w3, b3, g3, be3, m3, v3, H_DIM, 3);
    fcscale_kernel<<<1, 256>>>(wfc);
    pack_wfc_kernel<<<(C_OUT * NW) / 8, 256>>>(wfc);

    // 3 binary GEMM layers
    dim3 lgrid(B_ROWS / 64, 4);  // 128 row-tiles x 4 owgroups (8 warps each)
    layer_kernel<<<lgrid, 256>>>(1);   // xbits -> hA
    layer_kernel<<<lgrid, 256>>>(2);   // hA -> hB
    layer_kernel<<<lgrid, 256>>>(3);   // hB -> hA

    // final FC
    fc_kernel<<<B_ROWS / 8, 256>>>(bfc, out);
}

// round 4
// speedup vs baseline: 1.0483x; 1.0431x over previous
#include <cuda_runtime.h>
#include <stdint.h>

// Problem dims
#define B_ROWS 8192
#define D_IN   784
#define H_DIM  1024
#define C_OUT  10
#define NW     32          // 32-bit words per bit-row (1024 bits; x uses 25, rest zero-pad)

// ---------------- scratch (device globals; no allocation allowed) ----------------
__device__ uint32_t g_xbits[B_ROWS * NW];
__device__ uint32_t g_hA[B_ROWS * NW];
__device__ uint32_t g_hB[B_ROWS * NW];
__device__ uint32_t g_wt1[NW * H_DIM];   // transposed: [k][o]
__device__ uint32_t g_wt2[NW * H_DIM];
__device__ uint32_t g_wt3[NW * H_DIM];
__device__ float    g_P1[H_DIM];
__device__ float    g_P2[H_DIM];
__device__ float    g_P3[H_DIM];
__device__ uint32_t g_wfcb[C_OUT * NW];
__device__ float    g_sfc;

// ---------------- input packing: bit = (x >= 0.5)  (sign(2x-1), sign(0)=+1) ------
__global__ void pack_x_kernel(const float* __restrict__ x) {
    int wg   = (blockIdx.x * blockDim.x + threadIdx.x) >> 5;  // global warp id
    int lane = threadIdx.x & 31;
    int row  = wg >> 5;         // /32 words per row
    int k    = wg & 31;
    int f    = k * 32 + lane;
    unsigned pred = 0;
    if (f < D_IN) pred = (x[row * D_IN + f] >= 0.5f) ? 1u : 0u;
    unsigned word = __ballot_sync(0xFFFFFFFFu, pred);
    if (lane == 0) g_xbits[row * NW + k] = word;
}

// ---------------- weight packing (transposed [k][o]), bit = (w >= 0) -------------
__global__ void pack_w_kernel(const float* __restrict__ w, int K, int layer) {
    uint32_t* WT = (layer == 1) ? g_wt1 : (layer == 2) ? g_wt2 : g_wt3;
    int wg   = (blockIdx.x * blockDim.x + threadIdx.x) >> 5;
    int lane = threadIdx.x & 31;
    int o    = wg >> 5;
    int k    = wg & 31;
    int f    = k * 32 + lane;
    unsigned pred = 0;
    if (f < K) pred = (w[o * K + f] >= 0.0f) ? 1u : 0u;
    unsigned word = __ballot_sync(0xFFFFFFFFu, pred);
    if (lane == 0) WT[k * H_DIM + o] = word;
}

// ---------------- per-channel popcount thresholds --------------------------------
// y = (h - m)*g*rsqrt(v+eps) + be >= 0, h = scale*d + b, d = K - 2p
// ->  bit = ( p <= (K - T)/2 ),  T = (m - be/rg - b)/scale
__global__ void thr_kernel(const float* __restrict__ w, const float* __restrict__ b,
                           const float* __restrict__ g, const float* __restrict__ be,
                           const float* __restrict__ m, const float* __restrict__ v,
                           int K, int layer) {
    __shared__ float sm[256];
    int o = blockIdx.x;
    float s = 0.0f;
    for (int i = threadIdx.x; i < K; i += 256) s += fabsf(w[o * K + i]);
    sm[threadIdx.x] = s;
    __syncthreads();
    for (int off = 128; off > 0; off >>= 1) {
        if (threadIdx.x < off) sm[threadIdx.x] += sm[threadIdx.x + off];
        __syncthreads();
    }
    if (threadIdx.x == 0) {
        float* P = (layer == 1) ? g_P1 : (layer == 2) ? g_P2 : g_P3;
        float sc = sm[0] / (float)K;
        float rg = g[o] * rsqrtf(v[o] + 1e-5f);
        float T  = (m[o] - be[o] / rg - b[o]) / sc;
        P[o] = ((float)K - T) * 0.5f;
    }
}

// ---------------- final-layer scale (per-tensor mean |wfc|) ----------------------
__global__ void fcscale_kernel(const float* __restrict__ wfc) {
    __shared__ float sm[256];
    float s = 0.0f;
    for (int i = threadIdx.x; i < C_OUT * H_DIM; i += 256) s += fabsf(wfc[i]);
    sm[threadIdx.x] = s;
    __syncthreads();
    for (int off = 128; off > 0; off >>= 1) {
        if (threadIdx.x < off) sm[threadIdx.x] += sm[threadIdx.x + off];
        __syncthreads();
    }
    if (threadIdx.x == 0) g_sfc = sm[0] / (float)(C_OUT * H_DIM);
}

__global__ void pack_wfc_kernel(const float* __restrict__ wfc) {
    int wg   = (blockIdx.x * blockDim.x + threadIdx.x) >> 5;  // 320 warps total
    int lane = threadIdx.x & 31;
    int c    = wg >> 5;
    int k    = wg & 31;
    int f    = k * 32 + lane;
    unsigned pred = (wfc[c * H_DIM + f] >= 0.0f) ? 1u : 0u;
    unsigned word = __ballot_sync(0xFFFFFFFFu, pred);
    if (lane == 0) g_wfcb[c * NW + k] = word;
}

// ---------------- hot kernel: bit-GEMM + BN/sign epilogue ------------------------
// Each warp owns one out-word (32 output channels, one per lane), keeps the 32
// transposed weight words in registers, and streams 64 rows. Row bits load as
// 8 uniform LDG.128 (L1 broadcast). Epilogue: float compare + ballot -> 1 STG.
__global__ void __launch_bounds__(256) layer_kernel(int layer) {
    const uint32_t* I  = (layer == 1) ? g_xbits : (layer == 2) ? g_hA : g_hB;
    uint32_t*       O  = (layer == 1) ? g_hA   : (layer == 2) ? g_hB : g_hA;
    const uint32_t* WT = (layer == 1) ? g_wt1  : (layer == 2) ? g_wt2 : g_wt3;
    const float*    P  = (layer == 1) ? g_P1   : (layer == 2) ? g_P2  : g_P3;

    int warp = threadIdx.x >> 5;
    int lane = threadIdx.x & 31;
    int ow   = blockIdx.y * 8 + warp;     // out-word index 0..31
    int row0 = blockIdx.x * 64;
    int o    = (ow << 5) + lane;          // this lane's output channel

    uint32_t w[32];
#pragma unroll
    for (int k = 0; k < 32; k++) w[k] = WT[k * H_DIM + o];
    float thr = P[o];

    for (int r = 0; r < 64; r++) {
        int row = row0 + r;
        const uint4* arow = reinterpret_cast<const uint4*>(I + row * NW);
        int a0 = 0, a1 = 0, a2 = 0, a3 = 0;
#pragma unroll
        for (int kk = 0; kk < 8; kk++) {
            uint4 a = __ldg(arow + kk);
            a0 += __popc(a.x ^ w[4 * kk + 0]);
            a1 += __popc(a.y ^ w[4 * kk + 1]);
            a2 += __popc(a.z ^ w[4 * kk + 2]);
            a3 += __popc(a.w ^ w[4 * kk + 3]);
        }
        int acc = (a0 + a1) + (a2 + a3);
        unsigned word = __ballot_sync(0xFFFFFFFFu, (float)acc <= thr);
        if (lane == 0) O[row * NW + ow] = word;
    }
}

// ---------------- final FC: out = sfc * (1024 - 2p) + bfc ------------------------
__global__ void fc_kernel(const float* __restrict__ bfc, float* __restrict__ out) {
    int warp = threadIdx.x >> 5;
    int lane = threadIdx.x & 31;
    int row  = blockIdx.x * 8 + warp;
    if (lane < C_OUT) {
        const uint4* arow = reinterpret_cast<const uint4*>(g_hA + row * NW);
        const uint32_t* wb = g_wfcb + lane * NW;
        int acc = 0;
#pragma unroll
        for (int kk = 0; kk < 8; kk++) {
            uint4 a = __ldg(arow + kk);
            acc += __popc(a.x ^ wb[4 * kk + 0]);
            acc += __popc(a.y ^ wb[4 * kk + 1]);
            acc += __popc(a.z ^ wb[4 * kk + 2]);
            acc += __popc(a.w ^ wb[4 * kk + 3]);
        }
        float d = (float)(H_DIM - 2 * acc);
        out[row * C_OUT + lane] = g_sfc * d + bfc[lane];
    }
}

// ---------------- launch --------------------------------------------------------
extern "C" void kernel_launch(void* const* d_in, const int* in_sizes, int n_in,
                              void* d_out, int out_size) {
    const float* x   = (const float*)d_in[0];
    const float* w1  = (const float*)d_in[1];
    const float* b1  = (const float*)d_in[2];
    const float* g1  = (const float*)d_in[3];
    const float* be1 = (const float*)d_in[4];
    const float* m1  = (const float*)d_in[5];
    const float* v1  = (const float*)d_in[6];
    const float* w2  = (const float*)d_in[7];
    const float* b2  = (const float*)d_in[8];
    const float* g2  = (const float*)d_in[9];
    const float* be2 = (const float*)d_in[10];
    const float* m2  = (const float*)d_in[11];
    const float* v2  = (const float*)d_in[12];
    const float* w3  = (const float*)d_in[13];
    const float* b3  = (const float*)d_in[14];
    const float* g3  = (const float*)d_in[15];
    const float* be3 = (const float*)d_in[16];
    const float* m3  = (const float*)d_in[17];
    const float* v3  = (const float*)d_in[18];
    const float* wfc = (const float*)d_in[19];
    const float* bfc = (const float*)d_in[20];
    float* out = (float*)d_out;

    // pack input bits: 8192*32 warps
    pack_x_kernel<<<(B_ROWS * NW) / 8, 256>>>(x);

    // pack weights (transposed) + thresholds
    pack_w_kernel<<<(H_DIM * NW) / 8, 256>>>(w1, D_IN, 1);
    pack_w_kernel<<<(H_DIM * NW) / 8, 256>>>(w2, H_DIM, 2);
    pack_w_kernel<<<(H_DIM * NW) / 8, 256>>>(w3, H_DIM, 3);
    thr_kernel<<<H_DIM, 256>>>(w1, b1, g1, be1, m1, v1, D_IN, 1);
    thr_kernel<<<H_DIM, 256>>>(w2, b2, g2, be2, m2, v2, H_DIM, 2);
    thr_kernel<<<H_DIM, 256>>>(w3, b3, g3, be3, m3, v3, H_DIM, 3);
    fcscale_kernel<<<1, 256>>>(wfc);
    pack_wfc_kernel<<<(C_OUT * NW) / 8, 256>>>(wfc);

    // 3 binary GEMM layers
    dim3 lgrid(B_ROWS / 64, 4);  // 128 row-tiles x 4 owgroups (8 warps each)
    layer_kernel<<<lgrid, 256>>>(1);   // xbits -> hA
    layer_kernel<<<lgrid, 256>>>(2);   // hA -> hB
    layer_kernel<<<lgrid, 256>>>(3);   // hB -> hA

    // final FC
    fc_kernel<<<B_ROWS / 8, 256>>>(bfc, out);
}

// round 5
// speedup vs baseline: 1.0491x; 1.0008x over previous
#include <cuda_runtime.h>
#include <stdint.h>

// Problem dims
#define B_ROWS 8192
#define D_IN   784
#define H_DIM  1024
#define C_OUT  10
#define NW     32          // 32-bit words per bit-row (1024 bits; x uses 25, rest zero-pad)

// ---------------- scratch (device globals; no allocation allowed) ----------------
__device__ uint32_t g_xbits[B_ROWS * NW];
__device__ uint32_t g_hA[B_ROWS * NW];
__device__ uint32_t g_hB[B_ROWS * NW];
__device__ uint32_t g_wt1[NW * H_DIM];   // transposed: [k][o]
__device__ uint32_t g_wt2[NW * H_DIM];
__device__ uint32_t g_wt3[NW * H_DIM];
__device__ float    g_P1[H_DIM];
__device__ float    g_P2[H_DIM];
__device__ float    g_P3[H_DIM];
__device__ uint32_t g_wfcb[C_OUT * NW];
__device__ float    g_sfc;

// ---------------- input packing: bit = (x >= 0.5)  (sign(2x-1), sign(0)=+1) ------
__global__ void pack_x_kernel(const float* __restrict__ x) {
    int wg   = (blockIdx.x * blockDim.x + threadIdx.x) >> 5;  // global warp id
    int lane = threadIdx.x & 31;
    int row  = wg >> 5;         // /32 words per row
    int k    = wg & 31;
    int f    = k * 32 + lane;
    unsigned pred = 0;
    if (f < D_IN) pred = (x[row * D_IN + f] >= 0.5f) ? 1u : 0u;
    unsigned word = __ballot_sync(0xFFFFFFFFu, pred);
    if (lane == 0) g_xbits[row * NW + k] = word;
}

// ---------------- weight packing (transposed [k][o]), bit = (w >= 0) -------------
__global__ void pack_w_kernel(const float* __restrict__ w, int K, int layer) {
    uint32_t* WT = (layer == 1) ? g_wt1 : (layer == 2) ? g_wt2 : g_wt3;
    int wg   = (blockIdx.x * blockDim.x + threadIdx.x) >> 5;
    int lane = threadIdx.x & 31;
    int o    = wg >> 5;
    int k    = wg & 31;
    int f    = k * 32 + lane;
    unsigned pred = 0;
    if (f < K) pred = (w[o * K + f] >= 0.0f) ? 1u : 0u;
    unsigned word = __ballot_sync(0xFFFFFFFFu, pred);
    if (lane == 0) WT[k * H_DIM + o] = word;
}

// ---------------- per-channel popcount thresholds --------------------------------
// y = (h - m)*g*rsqrt(v+eps) + be >= 0, h = scale*d + b, d = K - 2p
// ->  bit = ( p <= (K - T)/2 ),  T = (m - be/rg - b)/scale
__global__ void thr_kernel(const float* __restrict__ w, const float* __restrict__ b,
                           const float* __restrict__ g, const float* __restrict__ be,
                           const float* __restrict__ m, const float* __restrict__ v,
                           int K, int layer) {
    __shared__ float sm[256];
    int o = blockIdx.x;
    float s = 0.0f;
    for (int i = threadIdx.x; i < K; i += 256) s += fabsf(w[o * K + i]);
    sm[threadIdx.x] = s;
    __syncthreads();
    for (int off = 128; off > 0; off >>= 1) {
        if (threadIdx.x < off) sm[threadIdx.x] += sm[threadIdx.x + off];
        __syncthreads();
    }
    if (threadIdx.x == 0) {
        float* P = (layer == 1) ? g_P1 : (layer == 2) ? g_P2 : g_P3;
        float sc = sm[0] / (float)K;
        float rg = g[o] * rsqrtf(v[o] + 1e-5f);
        float T  = (m[o] - be[o] / rg - b[o]) / sc;
        P[o] = ((float)K - T) * 0.5f;
    }
}

// ---------------- final-layer scale (per-tensor mean |wfc|) ----------------------
__global__ void fcscale_kernel(const float* __restrict__ wfc) {
    __shared__ float sm[256];
    float s = 0.0f;
    for (int i = threadIdx.x; i < C_OUT * H_DIM; i += 256) s += fabsf(wfc[i]);
    sm[threadIdx.x] = s;
    __syncthreads();
    for (int off = 128; off > 0; off >>= 1) {
        if (threadIdx.x < off) sm[threadIdx.x] += sm[threadIdx.x + off];
        __syncthreads();
    }
    if (threadIdx.x == 0) g_sfc = sm[0] / (float)(C_OUT * H_DIM);
}

__global__ void pack_wfc_kernel(const float* __restrict__ wfc) {
    int wg   = (blockIdx.x * blockDim.x + threadIdx.x) >> 5;  // 320 warps total
    int lane = threadIdx.x & 31;
    int c    = wg >> 5;
    int k    = wg & 31;
    int f    = k * 32 + lane;
    unsigned pred = (wfc[c * H_DIM + f] >= 0.0f) ? 1u : 0u;
    unsigned word = __ballot_sync(0xFFFFFFFFu, pred);
    if (lane == 0) g_wfcb[c * NW + k] = word;
}

// ---------------- hot kernel: bit-GEMM + BN/sign epilogue ------------------------
// Each warp owns one out-word (32 output channels, one per lane), keeps the 32
// transposed weight words in registers, and streams 64 rows. Row bits load as
// 8 uniform LDG.128 (L1 broadcast). Epilogue: float compare + ballot -> 1 STG.
__global__ void __launch_bounds__(256) layer_kernel(int layer) {
    const uint32_t* I  = (layer == 1) ? g_xbits : (layer == 2) ? g_hA : g_hB;
    uint32_t*       O  = (layer == 1) ? g_hA   : (layer == 2) ? g_hB : g_hA;
    const uint32_t* WT = (layer == 1) ? g_wt1  : (layer == 2) ? g_wt2 : g_wt3;
    const float*    P  = (layer == 1) ? g_P1   : (layer == 2) ? g_P2  : g_P3;

    int warp = threadIdx.x >> 5;
    int lane = threadIdx.x & 31;
    int ow   = blockIdx.y * 8 + warp;     // out-word index 0..31
    int row0 = blockIdx.x * 64;
    int o    = (ow << 5) + lane;          // this lane's output channel

    uint32_t w[32];
#pragma unroll
    for (int k = 0; k < 32; k++) w[k] = WT[k * H_DIM + o];
    float thr = P[o];

    for (int r = 0; r < 64; r++) {
        int row = row0 + r;
        const uint4* arow = reinterpret_cast<const uint4*>(I + row * NW);
        int a0 = 0, a1 = 0, a2 = 0, a3 = 0;
#pragma unroll
        for (int kk = 0; kk < 8; kk++) {
            uint4 a = __ldg(arow + kk);
            a0 += __popc(a.x ^ w[4 * kk + 0]);
            a1 += __popc(a.y ^ w[4 * kk + 1]);
            a2 += __popc(a.z ^ w[4 * kk + 2]);
            a3 += __popc(a.w ^ w[4 * kk + 3]);
        }
        int acc = (a0 + a1) + (a2 + a3);
        unsigned word = __ballot_sync(0xFFFFFFFFu, (float)acc <= thr);
        if (lane == 0) O[row * NW + ow] = word;
    }
}

// ---------------- final FC: out = sfc * (1024 - 2p) + bfc ------------------------
__global__ void fc_kernel(const float* __restrict__ bfc, float* __restrict__ out) {
    int warp = threadIdx.x >> 5;
    int lane = threadIdx.x & 31;
    int row  = blockIdx.x * 8 + warp;
    if (lane < C_OUT) {
        const uint4* arow = reinterpret_cast<const uint4*>(g_hA + row * NW);
        const uint32_t* wb = g_wfcb + lane * NW;
        int acc = 0;
#pragma unroll
        for (int kk = 0; kk < 8; kk++) {
            uint4 a = __ldg(arow + kk);
            acc += __popc(a.x ^ wb[4 * kk + 0]);
            acc += __popc(a.y ^ wb[4 * kk + 1]);
            acc += __popc(a.z ^ wb[4 * kk + 2]);
            acc += __popc(a.w ^ wb[4 * kk + 3]);
        }
        float d = (float)(H_DIM - 2 * acc);
        out[row * C_OUT + lane] = g_sfc * d + bfc[lane];
    }
}

// ---------------- launch --------------------------------------------------------
extern "C" void kernel_launch(void* const* d_in, const int* in_sizes, int n_in,
                              void* d_out, int out_size) {
    const float* x   = (const float*)d_in[0];
    const float* w1  = (const float*)d_in[1];
    const float* b1  = (const float*)d_in[2];
    const float* g1  = (const float*)d_in[3];
    const float* be1 = (const float*)d_in[4];
    const float* m1  = (const float*)d_in[5];
    const float* v1  = (const float*)d_in[6];
    const float* w2  = (const float*)d_in[7];
    const float* b2  = (const float*)d_in[8];
    const float* g2  = (const float*)d_in[9];
    const float* be2 = (const float*)d_in[10];
    const float* m2  = (const float*)d_in[11];
    const float* v2  = (const float*)d_in[12];
    const float* w3  = (const float*)d_in[13];
    const float* b3  = (const float*)d_in[14];
    const float* g3  = (const float*)d_in[15];
    const float* be3 = (const float*)d_in[16];
    const float* m3  = (const float*)d_in[17];
    const float* v3  = (const float*)d_in[18];
    const float* wfc = (const float*)d_in[19];
    const float* bfc = (const float*)d_in[20];
    float* out = (float*)d_out;

    // pack input bits: 8192*32 warps
    pack_x_kernel<<<(B_ROWS * NW) / 8, 256>>>(x);

    // pack weights (transposed) + thresholds
    pack_w_kernel<<<(H_DIM * NW) / 8, 256>>>(w1, D_IN, 1);
    pack_w_kernel<<<(H_DIM * NW) / 8, 256>>>(w2, H_DIM, 2);
    pack_w_kernel<<<(H_DIM * NW) / 8, 256>>>(w3, H_DIM, 3);
    thr_kernel<<<H_DIM, 256>>>(w1, b1, g1, be1, m1, v1, D_IN, 1);
    thr_kernel<<<H_DIM, 256>>>(w2, b2, g2, be2, m2, v2, H_DIM, 2);
    thr_kernel<<<H_DIM, 256>>>(w3, b3, g3, be3, m3, v3, H_DIM, 3);
    fcscale_kernel<<<1, 256>>>(wfc);
    pack_wfc_kernel<<<(C_OUT * NW) / 8, 256>>>(wfc);

    // 3 binary GEMM layers
    dim3 lgrid(B_ROWS / 64, 4);  // 128 row-tiles x 4 owgroups (8 warps each)
    layer_kernel<<<lgrid, 256>>>(1);   // xbits -> hA
    layer_kernel<<<lgrid, 256>>>(2);   // hA -> hB
    layer_kernel<<<lgrid, 256>>>(3);   // hB -> hA

    // final FC
    fc_kernel<<<B_ROWS / 8, 256>>>(bfc, out);
}